// round 4
// baseline (speedup 1.0000x reference)
#include <cuda_runtime.h>
#include <math.h>

#define K 64
#define TMAX 512
#define NEGV (-10000.0f)

// Precomputed log-softmax transition matrix, trans[i*K + j] = score(i -> j)
__device__ float g_trans[K * K];

// ---------------------------------------------------------------------------
// Kernel 1: trans = log_softmax(A + inv_mask * NEG, axis=-1)
// p1/p2 are the two 4096-element inputs in unknown order; we detect which is
// the int {0,1} mask by bit pattern (uint32 <= 1 for every element). Gaussian
// float32 data cannot be all-{0,1} bit patterns.
// ---------------------------------------------------------------------------
__global__ void trans_kernel(const unsigned int* __restrict__ p1,
                             const unsigned int* __restrict__ p2) {
    __shared__ int s_p1_is_mask;
    int i = threadIdx.x;
    if (i == 0) s_p1_is_mask = 1;
    __syncthreads();

    int ok = 1;
#pragma unroll
    for (int j = 0; j < K; j++) {
        ok &= (p1[i * K + j] <= 1u);
    }
    if (!ok) atomicAnd(&s_p1_is_mask, 0);
    __syncthreads();

    const float* A;
    const int* inv_mask;
    if (s_p1_is_mask) {
        inv_mask = (const int*)p1;
        A = (const float*)p2;
    } else {
        inv_mask = (const int*)p2;
        A = (const float*)p1;
    }

    float x[K];
    float m = -INFINITY;
#pragma unroll
    for (int j = 0; j < K; j++) {
        float v = A[i * K + j] + (inv_mask[i * K + j] ? NEGV : 0.0f);
        x[j] = v;
        m = fmaxf(m, v);
    }
    float s = 0.0f;
#pragma unroll
    for (int j = 0; j < K; j++) {
        s += expf(x[j] - m);
    }
    float ls = logf(s);
#pragma unroll
    for (int j = 0; j < K; j++) {
        g_trans[i * K + j] = (x[j] - m) - ls;
    }
}

// ---------------------------------------------------------------------------
// Kernel 2: per-batch Viterbi. One block per batch, 64 threads (thread = state j).
//  - trans column j lives in 64 registers per thread
//  - alpha ping-pong in SMEM (broadcast reads)
//  - backpointers in SMEM (u8), backtracked in-block
//  - early exit at t = len (reference's where() freezes alpha beyond len,
//    and bp beyond len is never consumed by the backward pass)
// Output written as FLOAT32 (harness compares as float arrays).
// ---------------------------------------------------------------------------
__global__ void __launch_bounds__(K) viterbi_kernel(
    const float* __restrict__ unary,
    const int* __restrict__ lengths,
    float* __restrict__ out,
    int T) {
    __shared__ float s_alpha[2][K];
    __shared__ unsigned char s_bp[TMAX][K];
    __shared__ int s_last;

    const int b = blockIdx.x;
    const int j = threadIdx.x;

    int len = lengths[b];
    if (len > T) len = T;
    if (len > TMAX) len = TMAX;
    if (len < 1) len = 1;

    // trans column j -> registers
    float rt[K];
#pragma unroll
    for (int i = 0; i < K; i++) {
        rt[i] = g_trans[i * K + j];
    }

    // alpha0 = GO frame: 0 at index 1, NEG elsewhere
    s_alpha[0][j] = (j == 1) ? 0.0f : NEGV;
    __syncthreads();

    const float* ub = unary + (size_t)b * T * K;
    int pp = 0;
    float u = ub[j];  // unary for step t=1

    for (int t = 1; t <= len; ++t) {
        float u_next = (t < len) ? ub[t * K + j] : 0.0f;

        const float* al = s_alpha[pp];

        // argmax_i (alpha[i] + trans[i][j]), first-occurrence on ties.
        // 4 contiguous chunks for ILP; combining with strict '>' in chunk
        // order preserves first-index tie-breaking exactly (jnp.argmax).
        float b0 = -INFINITY, b1 = -INFINITY, b2 = -INFINITY, b3 = -INFINITY;
        int i0 = 0, i1 = 16, i2 = 32, i3 = 48;
#pragma unroll
        for (int i = 0; i < 16; i++) {
            float s0 = al[i] + rt[i];
            if (s0 > b0) { b0 = s0; i0 = i; }
            float s1 = al[16 + i] + rt[16 + i];
            if (s1 > b1) { b1 = s1; i1 = 16 + i; }
            float s2 = al[32 + i] + rt[32 + i];
            if (s2 > b2) { b2 = s2; i2 = 32 + i; }
            float s3 = al[48 + i] + rt[48 + i];
            if (s3 > b3) { b3 = s3; i3 = 48 + i; }
        }
        float best = b0;
        int bidx = i0;
        if (b1 > best) { best = b1; bidx = i1; }
        if (b2 > best) { best = b2; bidx = i2; }
        if (b3 > best) { best = b3; bidx = i3; }

        s_bp[t - 1][j] = (unsigned char)bidx;
        s_alpha[pp ^ 1][j] = best + u;
        __syncthreads();
        pp ^= 1;
        u = u_next;
    }

    // final argmax over states (first occurrence)
    if (j == 0) {
        float best = s_alpha[pp][0];
        int bi = 0;
#pragma unroll
        for (int i = 1; i < K; i++) {
            float v = s_alpha[pp][i];
            if (v > best) { best = v; bi = i; }
        }
        s_last = bi;
    }
    __syncthreads();

    const int last = s_last;
    float* ob = out + (size_t)b * T;
    const float lastf = (float)last;

    // out[i] = last for all i >= len-1 (tail beyond the masked region)
    for (int i = len - 1 + j; i < T; i += K) {
        ob[i] = lastf;
    }

    // backtrack: cur = last; for t = len..2: cur = bp[t-1][cur]; out[t-2] = cur
    if (j == 0) {
        int cur = last;
        for (int t = len; t >= 2; --t) {
            cur = s_bp[t - 1][cur];
            ob[t - 2] = (float)cur;
        }
    }
}

extern "C" void kernel_launch(void* const* d_in, const int* in_sizes, int n_in,
                              void* d_out, int out_size) {
    // Bind inputs by SIZE, not position, so any metadata ordering works.
    //   unary   : B*T*K elements (largest)
    //   lengths : B elements
    //   inv_mask, A : K*K = 4096 elements each (disambiguated on device)
    int idx_unary = 0;
    long long max_sz = -1;
    for (int i = 0; i < n_in; i++) {
        if ((long long)in_sizes[i] > max_sz) { max_sz = in_sizes[i]; idx_unary = i; }
    }
    int idx_sq[2] = {-1, -1};
    int idx_len = -1;
    for (int i = 0; i < n_in; i++) {
        if (i == idx_unary) continue;
        if (in_sizes[i] == K * K) {
            if (idx_sq[0] < 0) idx_sq[0] = i; else idx_sq[1] = i;
        } else {
            idx_len = i;
        }
    }

    const float* unary   = (const float*)d_in[idx_unary];
    const int*   lengths = (const int*)d_in[idx_len];
    const unsigned int* p1 = (const unsigned int*)d_in[idx_sq[0]];
    const unsigned int* p2 = (const unsigned int*)d_in[idx_sq[1]];
    float* out = (float*)d_out;

    int B = in_sizes[idx_len];                                // 1024
    int T = (int)(in_sizes[idx_unary] / ((long long)B * K));  // 512

    trans_kernel<<<1, K>>>(p1, p2);
    viterbi_kernel<<<B, K>>>(unary, lengths, out, T);
}

// round 6
// speedup vs baseline: 1.0098x; 1.0098x over previous
#include <cuda_runtime.h>
#include <math.h>

#define K 64
#define TMAX 512
#define BMAX 1024
#define NEGV (-10000.0f)

// Precomputed log-softmax transition matrix, trans[i*K + j] = score(i -> j)
__device__ float g_trans[K * K];
// Backpointer scratch: bp[b][t][j], u8. 33.5MB static device array.
__device__ unsigned char g_bp[(size_t)BMAX * TMAX * K];
// Final argmax state per batch
__device__ int g_last[BMAX];

// ---------------------------------------------------------------------------
// Kernel 1: trans = log_softmax(A + inv_mask * NEG, axis=-1)
// p1/p2 are the two 4096-element inputs in unknown order; detect the int {0,1}
// mask by bit pattern (uint32 <= 1 for every element).
// ---------------------------------------------------------------------------
__global__ void trans_kernel(const unsigned int* __restrict__ p1,
                             const unsigned int* __restrict__ p2) {
    __shared__ int s_p1_is_mask;
    int i = threadIdx.x;
    if (i == 0) s_p1_is_mask = 1;
    __syncthreads();

    int ok = 1;
#pragma unroll
    for (int j = 0; j < K; j++) {
        ok &= (p1[i * K + j] <= 1u);
    }
    if (!ok) atomicAnd(&s_p1_is_mask, 0);
    __syncthreads();

    const float* A;
    const int* inv_mask;
    if (s_p1_is_mask) {
        inv_mask = (const int*)p1;
        A = (const float*)p2;
    } else {
        inv_mask = (const int*)p2;
        A = (const float*)p1;
    }

    float x[K];
    float m = -INFINITY;
#pragma unroll
    for (int j = 0; j < K; j++) {
        float v = A[i * K + j] + (inv_mask[i * K + j] ? NEGV : 0.0f);
        x[j] = v;
        m = fmaxf(m, v);
    }
    float s = 0.0f;
#pragma unroll
    for (int j = 0; j < K; j++) {
        s += expf(x[j] - m);
    }
    float ls = logf(s);
#pragma unroll
    for (int j = 0; j < K; j++) {
        g_trans[i * K + j] = (x[j] - m) - ls;
    }
}

// ---------------------------------------------------------------------------
// Kernel 2: forward pass. One block per batch, 64 threads (thread = state j).
//  - trans column j in 64 registers
//  - alpha ping-pong in tiny SMEM (float4 loads)
//  - backpointers streamed to global scratch (coalesced u8 stores)
//  - 8 independent argmax chunks of 8 for ILP; strict '>' ascending order
//    preserves jnp.argmax first-occurrence tie-breaking exactly.
//  - early exit at t = len
// ---------------------------------------------------------------------------
__global__ void __launch_bounds__(K) viterbi_fwd(
    const float* __restrict__ unary,
    const int* __restrict__ lengths,
    int T) {
    __shared__ __align__(16) float s_alpha[2][K];

    const int b = blockIdx.x;
    const int j = threadIdx.x;

    int len = lengths[b];
    if (len > T) len = T;
    if (len > TMAX) len = TMAX;
    if (len < 1) len = 1;

    float rt[K];
#pragma unroll
    for (int i = 0; i < K; i++) {
        rt[i] = g_trans[i * K + j];
    }

    s_alpha[0][j] = (j == 1) ? 0.0f : NEGV;
    __syncthreads();

    const float* ub = unary + (size_t)b * T * K;
    unsigned char* bpb = g_bp + (size_t)b * TMAX * K;
    int pp = 0;
    float u = ub[j];  // unary for t=1

    for (int t = 1; t <= len; ++t) {
        float u_next = (t < len) ? ub[t * K + j] : 0.0f;

        const float4* al4 = (const float4*)s_alpha[pp];

        float best[8];
        int bidx[8];
#pragma unroll
        for (int c = 0; c < 8; c++) {
            float4 v0 = al4[2 * c];
            float4 v1 = al4[2 * c + 1];
            float sv0 = v0.x + rt[8 * c + 0];
            float sv1 = v0.y + rt[8 * c + 1];
            float sv2 = v0.z + rt[8 * c + 2];
            float sv3 = v0.w + rt[8 * c + 3];
            float sv4 = v1.x + rt[8 * c + 4];
            float sv5 = v1.y + rt[8 * c + 5];
            float sv6 = v1.z + rt[8 * c + 6];
            float sv7 = v1.w + rt[8 * c + 7];
            float bb = sv0; int bi = 8 * c;
            if (sv1 > bb) { bb = sv1; bi = 8 * c + 1; }
            if (sv2 > bb) { bb = sv2; bi = 8 * c + 2; }
            if (sv3 > bb) { bb = sv3; bi = 8 * c + 3; }
            if (sv4 > bb) { bb = sv4; bi = 8 * c + 4; }
            if (sv5 > bb) { bb = sv5; bi = 8 * c + 5; }
            if (sv6 > bb) { bb = sv6; bi = 8 * c + 6; }
            if (sv7 > bb) { bb = sv7; bi = 8 * c + 7; }
            best[c] = bb;
            bidx[c] = bi;
        }
        float bb = best[0];
        int bi = bidx[0];
#pragma unroll
        for (int c = 1; c < 8; c++) {
            if (best[c] > bb) { bb = best[c]; bi = bidx[c]; }
        }

        bpb[(size_t)(t - 1) * K + j] = (unsigned char)bi;
        s_alpha[pp ^ 1][j] = bb + u;
        __syncthreads();
        pp ^= 1;
        u = u_next;
    }

    // final argmax (first occurrence)
    if (j == 0) {
        float best = s_alpha[pp][0];
        int bi = 0;
#pragma unroll
        for (int i = 1; i < K; i++) {
            float v = s_alpha[pp][i];
            if (v > best) { best = v; bi = i; }
        }
        g_last[b] = bi;
    }
}

// ---------------------------------------------------------------------------
// Kernel 3: backtrack. One block per batch, 64 threads.
// Bulk-copies this batch's bp rows (<=32KB, L2-resident) into SMEM via
// float4, then chases the path in-SMEM. Also writes the tail fill.
// ---------------------------------------------------------------------------
__global__ void __launch_bounds__(K) viterbi_bwd(
    const int* __restrict__ lengths,
    float* __restrict__ out,
    int T) {
    __shared__ unsigned char s_bp[TMAX * K];

    const int b = blockIdx.x;
    const int j = threadIdx.x;

    int len = lengths[b];
    if (len > T) len = T;
    if (len > TMAX) len = TMAX;
    if (len < 1) len = 1;

    const float4* src = (const float4*)(g_bp + (size_t)b * TMAX * K);
    float4* dst = (float4*)s_bp;
    int n4 = len * (K / 16);  // rows 0..len-1, 4 float4s per row
    for (int i = j; i < n4; i += K) {
        dst[i] = src[i];
    }

    const int last = g_last[b];
    float* ob = out + (size_t)b * T;
    const float lastf = (float)last;

    // tail: out[i] = last for i >= len-1
    for (int i = len - 1 + j; i < T; i += K) {
        ob[i] = lastf;
    }
    __syncthreads();

    // chase: cur = last; for t = len..2: cur = bp[t-1][cur]; out[t-2] = cur
    if (j == 0) {
        int cur = last;
        for (int t = len; t >= 2; --t) {
            cur = s_bp[(t - 1) * K + cur];
            ob[t - 2] = (float)cur;
        }
    }
}

extern "C" void kernel_launch(void* const* d_in, const int* in_sizes, int n_in,
                              void* d_out, int out_size) {
    // Bind inputs by SIZE, not position.
    //   unary   : B*T*K elements (largest)
    //   lengths : B elements
    //   inv_mask, A : K*K = 4096 elements each (disambiguated on device)
    int idx_unary = 0;
    long long max_sz = -1;
    for (int i = 0; i < n_in; i++) {
        if ((long long)in_sizes[i] > max_sz) { max_sz = in_sizes[i]; idx_unary = i; }
    }
    int idx_sq[2] = {-1, -1};
    int idx_len = -1;
    for (int i = 0; i < n_in; i++) {
        if (i == idx_unary) continue;
        if (in_sizes[i] == K * K) {
            if (idx_sq[0] < 0) idx_sq[0] = i; else idx_sq[1] = i;
        } else {
            idx_len = i;
        }
    }

    const float* unary   = (const float*)d_in[idx_unary];
    const int*   lengths = (const int*)d_in[idx_len];
    const unsigned int* p1 = (const unsigned int*)d_in[idx_sq[0]];
    const unsigned int* p2 = (const unsigned int*)d_in[idx_sq[1]];
    float* out = (float*)d_out;

    int B = in_sizes[idx_len];                                // 1024
    int T = (int)(in_sizes[idx_unary] / ((long long)B * K));  // 512
    if (B > BMAX) B = BMAX;

    trans_kernel<<<1, K>>>(p1, p2);
    viterbi_fwd<<<B, K>>>(unary, lengths, T);
    viterbi_bwd<<<B, K>>>(lengths, out, T);
}

// round 9
// speedup vs baseline: 1.3117x; 1.2990x over previous
#include <cuda_runtime.h>
#include <math.h>

#define K 64
#define TMAX 512
#define BMAX 1024
#define NEGV (-10000.0f)

// transT[j][i] = trans[i][j] (log_softmax result, transposed)
__device__ float g_transT[K * K];
// alpha_t rows: slot (t-1) holds alpha after step t.  134 MB scratch.
__device__ float g_alpha[(size_t)BMAX * TMAX * K];
// Final argmax state per batch
__device__ int g_last[BMAX];

// ---------------------------------------------------------------------------
// Kernel 1: trans = log_softmax(A + inv_mask * NEG, axis=-1), stored transposed.
// p1/p2: the two 4096-element inputs in unknown order; the int {0,1} mask is
// detected by bit pattern (every uint32 <= 1).
// ---------------------------------------------------------------------------
__global__ void trans_kernel(const unsigned int* __restrict__ p1,
                             const unsigned int* __restrict__ p2) {
    __shared__ int s_p1_is_mask;
    int i = threadIdx.x;
    if (i == 0) s_p1_is_mask = 1;
    __syncthreads();

    int ok = 1;
#pragma unroll
    for (int j = 0; j < K; j++) {
        ok &= (p1[i * K + j] <= 1u);
    }
    if (!ok) atomicAnd(&s_p1_is_mask, 0);
    __syncthreads();

    const float* A;
    const int* inv_mask;
    if (s_p1_is_mask) {
        inv_mask = (const int*)p1;
        A = (const float*)p2;
    } else {
        inv_mask = (const int*)p2;
        A = (const float*)p1;
    }

    float x[K];
    float m = -INFINITY;
#pragma unroll
    for (int j = 0; j < K; j++) {
        float v = A[i * K + j] + (inv_mask[i * K + j] ? NEGV : 0.0f);
        x[j] = v;
        m = fmaxf(m, v);
    }
    float s = 0.0f;
#pragma unroll
    for (int j = 0; j < K; j++) {
        s += expf(x[j] - m);
    }
    float ls = logf(s);
#pragma unroll
    for (int j = 0; j < K; j++) {
        g_transT[j * K + i] = (x[j] - m) - ls;   // transposed store
    }
}

// ---------------------------------------------------------------------------
// Kernel 2: forward pass, MAX-ONLY (no argmax). One block per batch,
// 64 threads (thread = state j). fmaxf tree is exact and order-independent,
// so the max value is bit-identical to the reference's jnp.max(scores).
// Each new alpha row is streamed to g_alpha for the backward pass.
// ---------------------------------------------------------------------------
__global__ void __launch_bounds__(K, 8) viterbi_fwd(
    const float* __restrict__ unary,
    const int* __restrict__ lengths,
    int T) {
    __shared__ __align__(16) float s_alpha[2][K];

    const int b = blockIdx.x;
    const int j = threadIdx.x;

    int len = lengths[b];
    if (len > T) len = T;
    if (len > TMAX) len = TMAX;
    if (len < 1) len = 1;

    // trans column j = transT row j -> 64 registers (contiguous, vector loads)
    float rt[K];
    {
        const float4* r4 = (const float4*)(g_transT + j * K);
#pragma unroll
        for (int p = 0; p < K / 4; p++) {
            float4 v = r4[p];
            rt[4 * p + 0] = v.x;
            rt[4 * p + 1] = v.y;
            rt[4 * p + 2] = v.z;
            rt[4 * p + 3] = v.w;
        }
    }

    s_alpha[0][j] = (j == 1) ? 0.0f : NEGV;   // GO frame
    __syncthreads();

    const float* ub = unary + (size_t)b * T * K;
    float* ab = g_alpha + (size_t)b * TMAX * K;
    int pp = 0;
    float u = ub[j];  // unary for t=1

    for (int t = 1; t <= len; ++t) {
        float u_next = (t < len) ? ub[t * K + j] : 0.0f;

        const float4* al4 = (const float4*)s_alpha[pp];

        float m[8];
#pragma unroll
        for (int c = 0; c < 8; c++) {
            float4 v0 = al4[2 * c];
            float4 v1 = al4[2 * c + 1];
            float a0 = v0.x + rt[8 * c + 0];
            float a1 = v0.y + rt[8 * c + 1];
            float a2 = v0.z + rt[8 * c + 2];
            float a3 = v0.w + rt[8 * c + 3];
            float a4 = v1.x + rt[8 * c + 4];
            float a5 = v1.y + rt[8 * c + 5];
            float a6 = v1.z + rt[8 * c + 6];
            float a7 = v1.w + rt[8 * c + 7];
            m[c] = fmaxf(fmaxf(fmaxf(a0, a1), fmaxf(a2, a3)),
                         fmaxf(fmaxf(a4, a5), fmaxf(a6, a7)));
        }
        float best = fmaxf(fmaxf(fmaxf(m[0], m[1]), fmaxf(m[2], m[3])),
                           fmaxf(fmaxf(m[4], m[5]), fmaxf(m[6], m[7])));

        float anew = best + u;
        s_alpha[pp ^ 1][j] = anew;
        ab[(size_t)(t - 1) * K + j] = anew;   // slot t-1 = alpha_t
        __syncthreads();
        pp ^= 1;
        u = u_next;
    }

    // final argmax over states (first occurrence)
    if (j == 0) {
        float best = s_alpha[pp][0];
        int bi = 0;
#pragma unroll
        for (int i = 1; i < K; i++) {
            float v = s_alpha[pp][i];
            if (v > best) { best = v; bi = i; }
        }
        g_last[b] = bi;
    }
}

// ---------------------------------------------------------------------------
// Kernel 3: backward pass. One WARP per batch. Recomputes the needed
// backpointer per step: prev = argmax_i(alpha[t-1][i] + trans[i][tag]).
// FADDs are bit-identical to forward/reference; first-occurrence ties via
// monotonic float->u32 key + reduce_max + ballot + ffs (lowest i wins).
// Alpha rows are register-prefetched 8 rows ahead to hide DRAM latency.
// ---------------------------------------------------------------------------
__global__ void __launch_bounds__(32) viterbi_bwd(
    const int* __restrict__ lengths,
    float* __restrict__ out,
    int T) {
    __shared__ float s_tT[K * K];   // transT, 16KB

    const int b = blockIdx.x;
    const int k = threadIdx.x;

    int len = lengths[b];
    if (len > T) len = T;
    if (len > TMAX) len = TMAX;
    if (len < 1) len = 1;

    // load transT into smem (broadcast-hot in L2)
    {
        const float4* src = (const float4*)g_transT;
        float4* dst = (float4*)s_tT;
        for (int i = k; i < K * K / 4; i += 32) {
            dst[i] = src[i];
        }
    }

    const int last = g_last[b];
    float* ob = out + (size_t)b * T;
    const float lastf = (float)last;

    // tail: out[i] = last for i >= len-1
    for (int i = len - 1 + k; i < T; i += 32) {
        ob[i] = lastf;
    }
    __syncwarp();

    const float* ab = g_alpha + (size_t)b * TMAX * K;
    int cur = last;
    int t = len;

    // prefetch first chunk: steps t..t-7 use alpha slots t-2..t-9
    float alo[8], ahi[8];
#pragma unroll
    for (int q = 0; q < 8; q++) {
        int r = t - 2 - q;
        const float* p = ab + (size_t)(r >= 0 ? r : 0) * K;
        alo[q] = p[k];
        ahi[q] = p[k + 32];
    }

    while (t >= 2) {
        // prefetch next chunk (slots t-10 .. t-17)
        float plo[8], phi[8];
#pragma unroll
        for (int q = 0; q < 8; q++) {
            int r = t - 10 - q;
            const float* p = ab + (size_t)(r >= 0 ? r : 0) * K;
            plo[q] = p[k];
            phi[q] = p[k + 32];
        }

        // process up to 8 steps (t, t-1, ..., t-7), warp-uniform guard
#pragma unroll
        for (int q = 0; q < 8; q++) {
            if (t - q >= 2) {
                float tlo = s_tT[cur * K + k];
                float thi = s_tT[cur * K + k + 32];
                float f1 = alo[q] + tlo;
                float f2 = ahi[q] + thi;
                unsigned u1 = __float_as_uint(f1);
                u1 ^= ((unsigned)((int)u1 >> 31)) | 0x80000000u;
                unsigned u2 = __float_as_uint(f2);
                u2 ^= ((unsigned)((int)u2 >> 31)) | 0x80000000u;
                unsigned um = u1 > u2 ? u1 : u2;
                unsigned vm = __reduce_max_sync(0xffffffffu, um);
                unsigned b1 = __ballot_sync(0xffffffffu, u1 == vm);
                unsigned b2 = __ballot_sync(0xffffffffu, u2 == vm);
                cur = b1 ? (__ffs(b1) - 1) : (__ffs(b2) + 31);
                ob[t - q - 2] = (float)cur;
            }
        }

        t -= 8;
#pragma unroll
        for (int q = 0; q < 8; q++) {
            alo[q] = plo[q];
            ahi[q] = phi[q];
        }
    }
}

extern "C" void kernel_launch(void* const* d_in, const int* in_sizes, int n_in,
                              void* d_out, int out_size) {
    // Bind inputs by SIZE, not position.
    //   unary   : B*T*K elements (largest)
    //   lengths : B elements
    //   inv_mask, A : K*K = 4096 elements each (disambiguated on device)
    int idx_unary = 0;
    long long max_sz = -1;
    for (int i = 0; i < n_in; i++) {
        if ((long long)in_sizes[i] > max_sz) { max_sz = in_sizes[i]; idx_unary = i; }
    }
    int idx_sq[2] = {-1, -1};
    int idx_len = -1;
    for (int i = 0; i < n_in; i++) {
        if (i == idx_unary) continue;
        if (in_sizes[i] == K * K) {
            if (idx_sq[0] < 0) idx_sq[0] = i; else idx_sq[1] = i;
        } else {
            idx_len = i;
        }
    }

    const float* unary   = (const float*)d_in[idx_unary];
    const int*   lengths = (const int*)d_in[idx_len];
    const unsigned int* p1 = (const unsigned int*)d_in[idx_sq[0]];
    const unsigned int* p2 = (const unsigned int*)d_in[idx_sq[1]];
    float* out = (float*)d_out;

    int B = in_sizes[idx_len];                                // 1024
    int T = (int)(in_sizes[idx_unary] / ((long long)B * K));  // 512
    if (B > BMAX) B = BMAX;

    trans_kernel<<<1, K>>>(p1, p2);
    viterbi_fwd<<<B, K>>>(unary, lengths, T);
    viterbi_bwd<<<B, 32>>>(lengths, out, T);
}